// round 1
// baseline (speedup 1.0000x reference)
#include <cuda_runtime.h>
#include <cstdint>

#define N_POINTS_C 1048576
#define N_LEVELS_C 16
#define LOG2_T_C 19
#define T_C (1u << LOG2_T_C)
#define TMASK_C (T_C - 1u)

// int(16 * b^i), b = exp((ln 512 - ln 16)/15) = 2^(1/3), matching the
// reference's python construction exactly (double math, truncation).
__constant__ int c_res[N_LEVELS_C] = {
    16, 20, 25, 32, 40, 50, 64, 80, 101, 128, 161, 203, 256, 322, 406, 512
};

__global__ void __launch_bounds__(256, 8) hashgrid_kernel(
    const float* __restrict__ x,
    const float* __restrict__ emb,
    float* __restrict__ out)
{
    const int n = blockIdx.x * blockDim.x + threadIdx.x;
    if (n >= N_POINTS_C) return;

    const float px = x[3 * n + 0];
    const float py = x[3 * n + 1];
    const float pz = x[3 * n + 2];

    float acc[2 * N_LEVELS_C];

#pragma unroll
    for (int l = 0; l < N_LEVELS_C; l++) {
        const int res = c_res[l];
        const float rf = (float)(res - 1);

        const float sx = px * rf;
        const float sy = py * rf;
        const float sz = pz * rf;

        int fx = (int)sx; fx = fx > res - 2 ? res - 2 : fx; fx = fx < 0 ? 0 : fx;
        int fy = (int)sy; fy = fy > res - 2 ? res - 2 : fy; fy = fy < 0 ? 0 : fy;
        int fz = (int)sz; fz = fz > res - 2 ? res - 2 : fz; fz = fz < 0 ? 0 : fz;

        const float tx = sx - (float)fx;
        const float ty = sy - (float)fy;
        const float tz = sz - (float)fz;
        const float ux = 1.0f - tx;
        const float uy = 1.0f - ty;
        const float uz = 1.0f - tz;

        // Per-dimension hash components (dim0 prime = 1).
        const unsigned hx0 = (unsigned)fx;
        const unsigned hx1 = (unsigned)(fx + 1);
        const unsigned hy0 = (unsigned)fy * 2654435761u;
        const unsigned hy1 = hy0 + 2654435761u;
        const unsigned hz0 = (unsigned)fz * 805459861u;
        const unsigned hz1 = hz0 + 805459861u;

        const float2* __restrict__ tab =
            reinterpret_cast<const float2*>(emb) + (size_t)l * T_C;

        // Compute all 8 hashed indices first so the 8 gathers issue
        // back-to-back (MLP=8).
        unsigned h[8];
        h[0] = (hx0 ^ hy0 ^ hz0) & TMASK_C;
        h[1] = (hx1 ^ hy0 ^ hz0) & TMASK_C;
        h[2] = (hx0 ^ hy1 ^ hz0) & TMASK_C;
        h[3] = (hx1 ^ hy1 ^ hz0) & TMASK_C;
        h[4] = (hx0 ^ hy0 ^ hz1) & TMASK_C;
        h[5] = (hx1 ^ hy0 ^ hz1) & TMASK_C;
        h[6] = (hx0 ^ hy1 ^ hz1) & TMASK_C;
        h[7] = (hx1 ^ hy1 ^ hz1) & TMASK_C;

        float2 v[8];
#pragma unroll
        for (int c = 0; c < 8; c++) v[c] = __ldg(&tab[h[c]]);

        float w[8];
        w[0] = ux * uy * uz;
        w[1] = tx * uy * uz;
        w[2] = ux * ty * uz;
        w[3] = tx * ty * uz;
        w[4] = ux * uy * tz;
        w[5] = tx * uy * tz;
        w[6] = ux * ty * tz;
        w[7] = tx * ty * tz;

        float a0 = 0.0f, a1 = 0.0f;
#pragma unroll
        for (int c = 0; c < 8; c++) {
            a0 += w[c] * v[c].x;
            a1 += w[c] * v[c].y;
        }
        acc[2 * l + 0] = a0;
        acc[2 * l + 1] = a1;
    }

    float4* __restrict__ o = reinterpret_cast<float4*>(out + (size_t)n * 32);
#pragma unroll
    for (int i = 0; i < 8; i++) {
        o[i] = make_float4(acc[4 * i + 0], acc[4 * i + 1],
                           acc[4 * i + 2], acc[4 * i + 3]);
    }
}

extern "C" void kernel_launch(void* const* d_in, const int* in_sizes, int n_in,
                              void* d_out, int out_size)
{
    const float* x = (const float*)d_in[0];
    const float* emb = (const float*)d_in[1];
    float* out = (float*)d_out;

    const int threads = 256;
    const int blocks = (N_POINTS_C + threads - 1) / threads;
    hashgrid_kernel<<<blocks, threads>>>(x, emb, out);
}

// round 2
// speedup vs baseline: 1.4323x; 1.4323x over previous
#include <cuda_runtime.h>
#include <cstdint>

#define N_POINTS_C 1048576
#define N_LEVELS_C 16
#define LOG2_T_C 19
#define T_C (1u << LOG2_T_C)
#define TMASK_C (T_C - 1u)

#define NBUCKETS 32768   // 32^3 spatial buckets, ~32 points each

__constant__ int c_res[N_LEVELS_C] = {
    16, 20, 25, 32, 40, 50, 64, 80, 101, 128, 161, 203, 256, 322, 406, 512
};

// Scratch (device globals: allocation-free).
__device__ unsigned int g_hist[NBUCKETS];
__device__ unsigned int g_offs[NBUCKETS];
__device__ float4       g_xs[N_POINTS_C];   // sorted (x,y,z, orig-idx-bits)

__device__ __forceinline__ int bucket_of(float px, float py, float pz) {
    int bx = (int)(px * 32.0f); bx = bx > 31 ? 31 : (bx < 0 ? 0 : bx);
    int by = (int)(py * 32.0f); by = by > 31 ? 31 : (by < 0 ? 0 : by);
    int bz = (int)(pz * 32.0f); bz = bz > 31 ? 31 : (bz < 0 ? 0 : bz);
    return (bz << 10) | (by << 5) | bx;
}

__global__ void zero_hist_kernel() {
    int i = blockIdx.x * blockDim.x + threadIdx.x;
    if (i < NBUCKETS) g_hist[i] = 0u;
}

__global__ void hist_kernel(const float* __restrict__ x) {
    int n = blockIdx.x * blockDim.x + threadIdx.x;
    if (n >= N_POINTS_C) return;
    float px = x[3 * n + 0], py = x[3 * n + 1], pz = x[3 * n + 2];
    atomicAdd(&g_hist[bucket_of(px, py, pz)], 1u);
}

// Exclusive prefix sum over 32768 bins: 1 block of 1024 threads, 32 bins each.
__global__ void scan_kernel() {
    __shared__ unsigned int part[1024];
    const int t = threadIdx.x;
    unsigned int local[32];
    unsigned int s = 0;
#pragma unroll
    for (int j = 0; j < 32; j++) {
        local[j] = s;                 // exclusive within chunk
        s += g_hist[t * 32 + j];
    }
    part[t] = s;
    __syncthreads();
    // Hillis-Steele inclusive scan of the 1024 partials
    for (int d = 1; d < 1024; d <<= 1) {
        unsigned int v = part[t];
        unsigned int add = (t >= d) ? part[t - d] : 0u;
        __syncthreads();
        part[t] = v + add;
        __syncthreads();
    }
    unsigned int base = (t == 0) ? 0u : part[t - 1]; // exclusive
#pragma unroll
    for (int j = 0; j < 32; j++)
        g_offs[t * 32 + j] = base + local[j];
}

__global__ void scatter_kernel(const float* __restrict__ x) {
    int n = blockIdx.x * blockDim.x + threadIdx.x;
    if (n >= N_POINTS_C) return;
    float px = x[3 * n + 0], py = x[3 * n + 1], pz = x[3 * n + 2];
    int b = bucket_of(px, py, pz);
    unsigned int pos = atomicAdd(&g_offs[b], 1u);
    g_xs[pos] = make_float4(px, py, pz, __int_as_float(n));
}

__global__ void __launch_bounds__(256, 8) hashgrid_kernel(
    const float* __restrict__ emb,
    float* __restrict__ out)
{
    const int n = blockIdx.x * blockDim.x + threadIdx.x;
    if (n >= N_POINTS_C) return;

    const float4 p = g_xs[n];
    const float px = p.x, py = p.y, pz = p.z;
    const int  oidx = __float_as_int(p.w);

    float acc[2 * N_LEVELS_C];

#pragma unroll
    for (int l = 0; l < N_LEVELS_C; l++) {
        const int res = c_res[l];
        const float rf = (float)(res - 1);

        const float sx = px * rf;
        const float sy = py * rf;
        const float sz = pz * rf;

        int fx = (int)sx; fx = fx > res - 2 ? res - 2 : fx; fx = fx < 0 ? 0 : fx;
        int fy = (int)sy; fy = fy > res - 2 ? res - 2 : fy; fy = fy < 0 ? 0 : fy;
        int fz = (int)sz; fz = fz > res - 2 ? res - 2 : fz; fz = fz < 0 ? 0 : fz;

        const float tx = sx - (float)fx;
        const float ty = sy - (float)fy;
        const float tz = sz - (float)fz;
        const float ux = 1.0f - tx;
        const float uy = 1.0f - ty;
        const float uz = 1.0f - tz;

        const unsigned hx0 = (unsigned)fx;
        const unsigned hx1 = (unsigned)(fx + 1);
        const unsigned hy0 = (unsigned)fy * 2654435761u;
        const unsigned hy1 = hy0 + 2654435761u;
        const unsigned hz0 = (unsigned)fz * 805459861u;
        const unsigned hz1 = hz0 + 805459861u;

        const float2* __restrict__ tab =
            reinterpret_cast<const float2*>(emb) + (size_t)l * T_C;

        unsigned h[8];
        h[0] = (hx0 ^ hy0 ^ hz0) & TMASK_C;
        h[1] = (hx1 ^ hy0 ^ hz0) & TMASK_C;
        h[2] = (hx0 ^ hy1 ^ hz0) & TMASK_C;
        h[3] = (hx1 ^ hy1 ^ hz0) & TMASK_C;
        h[4] = (hx0 ^ hy0 ^ hz1) & TMASK_C;
        h[5] = (hx1 ^ hy0 ^ hz1) & TMASK_C;
        h[6] = (hx0 ^ hy1 ^ hz1) & TMASK_C;
        h[7] = (hx1 ^ hy1 ^ hz1) & TMASK_C;

        float2 v[8];
#pragma unroll
        for (int c = 0; c < 8; c++) v[c] = __ldg(&tab[h[c]]);

        float w[8];
        w[0] = ux * uy * uz;
        w[1] = tx * uy * uz;
        w[2] = ux * ty * uz;
        w[3] = tx * ty * uz;
        w[4] = ux * uy * tz;
        w[5] = tx * uy * tz;
        w[6] = ux * ty * tz;
        w[7] = tx * ty * tz;

        float a0 = 0.0f, a1 = 0.0f;
#pragma unroll
        for (int c = 0; c < 8; c++) {
            a0 += w[c] * v[c].x;
            a1 += w[c] * v[c].y;
        }
        acc[2 * l + 0] = a0;
        acc[2 * l + 1] = a1;
    }

    float4* __restrict__ o = reinterpret_cast<float4*>(out + (size_t)oidx * 32);
#pragma unroll
    for (int i = 0; i < 8; i++) {
        o[i] = make_float4(acc[4 * i + 0], acc[4 * i + 1],
                           acc[4 * i + 2], acc[4 * i + 3]);
    }
}

extern "C" void kernel_launch(void* const* d_in, const int* in_sizes, int n_in,
                              void* d_out, int out_size)
{
    const float* x = (const float*)d_in[0];
    const float* emb = (const float*)d_in[1];
    float* out = (float*)d_out;

    const int threads = 256;
    const int pblocks = (N_POINTS_C + threads - 1) / threads;

    zero_hist_kernel<<<(NBUCKETS + 255) / 256, 256>>>();
    hist_kernel<<<pblocks, threads>>>(x);
    scan_kernel<<<1, 1024>>>();
    scatter_kernel<<<pblocks, threads>>>(x);
    hashgrid_kernel<<<pblocks, threads>>>(emb, out);
}